// round 2
// baseline (speedup 1.0000x reference)
#include <cuda_runtime.h>
#include <math.h>

#define NB 8
#define NM 4
#define NT 2048
#define NE 768
#define NP 256
#define NKD 64
#define NVD 64
#define NH 128
#define NX 16
#define NCOMB 384
#define NMLP 192
#define NTOK (NB*NM*NT)   /* 65536 */

// ---------------- scratch (device globals: no runtime alloc allowed) --------
__device__ float g_processed[(size_t)NTOK*NP];   // 64 MB
__device__ float g_hid[(size_t)NTOK*NMLP];       // 48 MB
__device__ float g_scal[(size_t)NTOK*2];         // Ar, As per token
__device__ float g_rus[(size_t)NTOK*NH];         // 32 MB
__device__ float g_wa[NP], g_wb[NP], g_wc[NP];
__device__ float g_cc[3];
__device__ float g_c0[3*NH], g_c1[3*NH], g_c2[3*NH], g_c3[3*NH];

// ---------------- f32x2 helpers ---------------------------------------------
__device__ __forceinline__ unsigned long long ffma2(unsigned long long a,
                                                    unsigned long long b,
                                                    unsigned long long c) {
    unsigned long long d;
    asm("fma.rn.f32x2 %0, %1, %2, %3;" : "=l"(d) : "l"(a), "l"(b), "l"(c));
    return d;
}
__device__ __forceinline__ unsigned long long pack2(float x, float y) {
    unsigned long long d;
    asm("mov.b64 %0, {%1, %2};" : "=l"(d) : "f"(x), "f"(y));
    return d;
}
__device__ __forceinline__ float lo2(unsigned long long v) { return __uint_as_float((unsigned)v); }
__device__ __forceinline__ float hi2(unsigned long long v) { return __uint_as_float((unsigned)(v >> 32)); }

// ---------------- precompute folded weight vectors (1 block) ----------------
__global__ void __launch_bounds__(384) k_pre(
                      const float* __restrict__ qw, const float* __restrict__ qb,
                      const float* __restrict__ kw, const float* __restrict__ kb,
                      const float* __restrict__ wih, const float* __restrict__ bih,
                      const float* __restrict__ vw, const float* __restrict__ vb) {
    int i = threadIdx.x;
    if (i < NP) {
        float a = 0.f, b = 0.f, c = 0.f;
#pragma unroll 4
        for (int k = 0; k < NKD; k++) {
            float q = qw[k*NP + i];
            a = fmaf(q, kw[2*k], a);
            b = fmaf(q, kw[2*k+1], b);
            c = fmaf(q, kb[k], c);
        }
        g_wa[i] = a; g_wb[i] = b; g_wc[i] = c;
    }
    if (i == 0) {
        float a = 0.f, b = 0.f, c = 0.f;
#pragma unroll 4
        for (int k = 0; k < NKD; k++) {
            float q = qb[k];
            a = fmaf(q, kw[2*k], a);
            b = fmaf(q, kw[2*k+1], b);
            c = fmaf(q, kb[k], c);
        }
        g_cc[0] = a; g_cc[1] = b; g_cc[2] = c;
    }
    if (i < 3*NH) {
        const float* wr = wih + (size_t)i*(1 + NVD);
        float c1 = 0.f, c2 = 0.f, c3 = bih[i];
#pragma unroll 4
        for (int v = 0; v < NVD; v++) {
            float w = wr[1 + v];
            c1 = fmaf(w, vw[2*v], c1);
            c2 = fmaf(w, vw[2*v+1], c2);
            c3 = fmaf(w, vb[v], c3);
        }
        g_c0[i] = wr[0]; g_c1[i] = c1; g_c2[i] = c2; g_c3[i] = c3;
    }
}

// ---------------- generic C = relu(A @ W^T + bias) --------------------------
// A logically [M x K], physically split: cols [0,K1) from A1 (row stride K1),
// cols [K1,K) from A2 (row stride K-K1). W is [N x K] row-major.
// 64x64 tile, BK=16, 256 threads, 4x4 micro-tile, f32x2 accumulation.
__global__ void __launch_bounds__(256) k_gemm_relu(
    const float* __restrict__ A1, int K1, const float* __restrict__ A2,
    const float* __restrict__ W, const float* __restrict__ bias,
    float* __restrict__ C, int N, int K) {
    __shared__ __align__(16) float As[16][64];
    __shared__ __align__(16) float Bs[16][64];
    const int m0 = blockIdx.y << 6, n0 = blockIdx.x << 6;
    const int tid = threadIdx.x;
    const int tx = tid & 15, ty = tid >> 4;
    const int lr = tid >> 2, lc = (tid & 3) << 2;

    unsigned long long acc[2][4];
#pragma unroll
    for (int p = 0; p < 2; p++)
#pragma unroll
        for (int c = 0; c < 4; c++) acc[p][c] = 0ull;

    for (int k0 = 0; k0 < K; k0 += 16) {
        const float* Ab; int strideA, acol;
        if (k0 < K1) { Ab = A1; strideA = K1; acol = k0; }
        else         { Ab = A2; strideA = K - K1; acol = k0 - K1; }
        float4 av = *(const float4*)&Ab[(size_t)(m0 + lr) * strideA + acol + lc];
        float4 bv = *(const float4*)&W[(size_t)(n0 + lr) * K + k0 + lc];
        __syncthreads();
        As[lc+0][lr] = av.x; As[lc+1][lr] = av.y; As[lc+2][lr] = av.z; As[lc+3][lr] = av.w;
        Bs[lc+0][lr] = bv.x; Bs[lc+1][lr] = bv.y; Bs[lc+2][lr] = bv.z; Bs[lc+3][lr] = bv.w;
        __syncthreads();
#pragma unroll
        for (int kk = 0; kk < 16; kk++) {
            ulonglong2 a2 = *(const ulonglong2*)&As[kk][ty << 2];
            float4 b4 = *(const float4*)&Bs[kk][tx << 2];
            unsigned long long bb0 = pack2(b4.x, b4.x);
            unsigned long long bb1 = pack2(b4.y, b4.y);
            unsigned long long bb2 = pack2(b4.z, b4.z);
            unsigned long long bb3 = pack2(b4.w, b4.w);
            acc[0][0] = ffma2(a2.x, bb0, acc[0][0]);
            acc[1][0] = ffma2(a2.y, bb0, acc[1][0]);
            acc[0][1] = ffma2(a2.x, bb1, acc[0][1]);
            acc[1][1] = ffma2(a2.y, bb1, acc[1][1]);
            acc[0][2] = ffma2(a2.x, bb2, acc[0][2]);
            acc[1][2] = ffma2(a2.y, bb2, acc[1][2]);
            acc[0][3] = ffma2(a2.x, bb3, acc[0][3]);
            acc[1][3] = ffma2(a2.y, bb3, acc[1][3]);
        }
    }
    float4 bias4 = *(const float4*)&bias[n0 + (tx << 2)];
#pragma unroll
    for (int r = 0; r < 4; r++) {
        int p = r >> 1;
        bool hi = (r & 1);
        float4 v;
        v.x = (hi ? hi2(acc[p][0]) : lo2(acc[p][0])) + bias4.x;
        v.y = (hi ? hi2(acc[p][1]) : lo2(acc[p][1])) + bias4.y;
        v.z = (hi ? hi2(acc[p][2]) : lo2(acc[p][2])) + bias4.z;
        v.w = (hi ? hi2(acc[p][3]) : lo2(acc[p][3])) + bias4.w;
        v.x = fmaxf(v.x, 0.f); v.y = fmaxf(v.y, 0.f);
        v.z = fmaxf(v.z, 0.f); v.w = fmaxf(v.w, 0.f);
        *(float4*)&C[(size_t)(m0 + (ty << 2) + r) * N + n0 + (tx << 2)] = v;
    }
}

// ---------------- per-token attention scalars (Ar, As) ----------------------
__global__ void __launch_bounds__(256) k_scal(const float* __restrict__ R,
                                              const float* __restrict__ S) {
    int warp = (blockIdx.x * blockDim.x + threadIdx.x) >> 5;
    int lane = threadIdx.x & 31;
    if (warp >= NTOK) return;
    int tok = warp;
    const float* pr = g_processed + (size_t)tok * NP;
    float aa = 0.f, ab = 0.f, ac = 0.f;
#pragma unroll
    for (int p = lane; p < NP; p += 32) {
        float pv = pr[p];
        aa = fmaf(pv, g_wa[p], aa);
        ab = fmaf(pv, g_wb[p], ab);
        ac = fmaf(pv, g_wc[p], ac);
    }
#pragma unroll
    for (int o = 16; o; o >>= 1) {
        aa += __shfl_down_sync(0xffffffffu, aa, o);
        ab += __shfl_down_sync(0xffffffffu, ab, o);
        ac += __shfl_down_sync(0xffffffffu, ac, o);
    }
    if (lane == 0) {
        aa += g_cc[0]; ab += g_cc[1]; ac += g_cc[2];
        int t = tok & (NT - 1);
        int s = tok >> 11;          // b*4+m
        int m = s & 3;
        float sc[3], Ro[3], So[3];
        int n = 0;
        for (int j = 0; j < NM; j++) {
            if (j == m) continue;
            size_t idx = ((size_t)s * NM + j) * NT + t;
            float r = R[idx], sv = S[idx];
            Ro[n] = r; So[n] = sv;
            sc[n] = (fmaf(aa, r, fmaf(ab, sv, ac))) * 0.125f;
            n++;
        }
        float mx = fmaxf(sc[0], fmaxf(sc[1], sc[2]));
        float e0 = expf(sc[0] - mx), e1 = expf(sc[1] - mx), e2 = expf(sc[2] - mx);
        float inv = 1.f / (e0 + e1 + e2);
        g_scal[2*tok]   = (e0*Ro[0] + e1*Ro[1] + e2*Ro[2]) * inv;
        g_scal[2*tok+1] = (e0*So[0] + e1*So[1] + e2*So[2]) * inv;
    }
}

// ---------------- GRU scan: one block per sequence (32 blocks) --------------
// 384 threads: thread i owns row i of w_hh (in registers, as 64 f32x2 pairs).
__global__ void __launch_bounds__(384, 1) k_gru(const float* __restrict__ U,
                                                const float* __restrict__ whh,
                                                const float* __restrict__ bhh) {
    __shared__ __align__(16) float hbuf[NH];
    __shared__ float exch[3*NH];
    __shared__ float exch_xn[NH];
    __shared__ float su[512], sar[512], sas[512];
    const int s = blockIdx.x;
    const int i = threadIdx.x;

    unsigned long long w2r[NH/2];
    const unsigned long long* wp = (const unsigned long long*)(whh + (size_t)i * NH);
#pragma unroll
    for (int k = 0; k < NH/2; k++) w2r[k] = wp[k];
    const float bb = bhh[i];
    const float c0 = g_c0[i], c1 = g_c1[i], c2 = g_c2[i], c3 = g_c3[i];

    if (i < NH) hbuf[i] = 0.f;
    const size_t base = (size_t)s * NT;
    float* outp = g_rus + base * NH + i;   // valid only for i < NH

    for (int t0 = 0; t0 < NT; t0 += 512) {
        __syncthreads();
        for (int j = i; j < 512; j += 384) {
            size_t g = base + t0 + j;
            su[j]  = U[g];
            sar[j] = g_scal[2*g];
            sas[j] = g_scal[2*g + 1];
        }
        __syncthreads();
        for (int tt = 0; tt < 512; tt++) {
            float xt = fmaf(su[tt], c0, fmaf(sar[tt], c1, fmaf(sas[tt], c2, c3)));
            unsigned long long a0 = 0ull, a1 = 0ull;
#pragma unroll
            for (int k = 0; k < NH/4; k++) {
                ulonglong2 hv = *(const ulonglong2*)&hbuf[k << 2];
                a0 = ffma2(w2r[2*k],   hv.x, a0);
                a1 = ffma2(w2r[2*k+1], hv.y, a1);
            }
            float acc = bb + ((lo2(a0) + hi2(a0)) + (lo2(a1) + hi2(a1)));
            if (i < 2*NH) exch[i] = acc + xt;
            else { exch[i] = acc; exch_xn[i - 2*NH] = xt; }
            __syncthreads();
            if (i < NH) {
                float r = __fdividef(1.f, 1.f + __expf(-exch[i]));
                float z = __fdividef(1.f, 1.f + __expf(-exch[NH + i]));
                float nn = tanhf(fmaf(r, exch[2*NH + i], exch_xn[i]));
                float hnew = fmaf(z, hbuf[i] - nn, nn);   // (1-z)*n + z*h
                outp[(size_t)(t0 + tt) * NH] = hnew;
                hbuf[i] = hnew;
            }
            __syncthreads();
        }
    }
}

// ---------------- final 192 -> 16 projection --------------------------------
__global__ void __launch_bounds__(256) k_mlp2(const float* __restrict__ w2,
                                              const float* __restrict__ b2,
                                              float* __restrict__ out) {
    __shared__ __align__(16) float sh[16][196];
    __shared__ __align__(16) float sw[16][196];
    const int tid = threadIdx.x;
    const int tok0 = blockIdx.x << 4;
    for (int idx = tid; idx < 16*NMLP; idx += 256) {
        int e = idx / NMLP, k = idx - e*NMLP;
        sw[e][k] = w2[idx];
    }
    for (int idx = tid; idx < 16*NMLP; idx += 256) {
        int r = idx / NMLP, k = idx - r*NMLP;
        sh[r][k] = g_hid[(size_t)(tok0 + r) * NMLP + k];
    }
    __syncthreads();
    const int e = tid & 15, r = tid >> 4;
    float acc = b2[e];
#pragma unroll
    for (int k = 0; k < NMLP; k += 4) {
        float4 hv = *(const float4*)&sh[r][k];
        float4 wv = *(const float4*)&sw[e][k];
        acc = fmaf(hv.x, wv.x, acc);
        acc = fmaf(hv.y, wv.y, acc);
        acc = fmaf(hv.z, wv.z, acc);
        acc = fmaf(hv.w, wv.w, acc);
    }
    out[(size_t)(tok0 + r) * NX + e] = acc;
}

// ---------------- launch ----------------------------------------------------
extern "C" void kernel_launch(void* const* d_in, const int* in_sizes, int n_in,
                              void* d_out, int out_size) {
    const float* emb  = (const float*)d_in[0];
    const float* U    = (const float*)d_in[1];
    const float* R    = (const float*)d_in[2];
    const float* S    = (const float*)d_in[3];
    const float* tp_w = (const float*)d_in[4];
    const float* tp_b = (const float*)d_in[5];
    const float* q_w  = (const float*)d_in[6];
    const float* q_b  = (const float*)d_in[7];
    const float* k_w  = (const float*)d_in[8];
    const float* k_b  = (const float*)d_in[9];
    const float* v_w  = (const float*)d_in[10];
    const float* v_b  = (const float*)d_in[11];
    const float* wih  = (const float*)d_in[12];
    const float* whh  = (const float*)d_in[13];
    const float* bih  = (const float*)d_in[14];
    const float* bhh  = (const float*)d_in[15];
    const float* w1   = (const float*)d_in[16];
    const float* b1   = (const float*)d_in[17];
    const float* w2   = (const float*)d_in[18];
    const float* b2   = (const float*)d_in[19];
    float* out = (float*)d_out;

    float *processed, *hid, *rus;
    cudaGetSymbolAddress((void**)&processed, g_processed);
    cudaGetSymbolAddress((void**)&hid, g_hid);
    cudaGetSymbolAddress((void**)&rus, g_rus);

    k_pre<<<1, 384>>>(q_w, q_b, k_w, k_b, wih, bih, v_w, v_b);
    k_gemm_relu<<<dim3(NP/64, NTOK/64), 256>>>(emb, NE, emb, tp_w, tp_b,
                                               processed, NP, NE);
    k_scal<<<NTOK/8, 256>>>(R, S);
    k_gru<<<NB*NM, 384>>>(U, whh, bhh);
    k_gemm_relu<<<dim3(NMLP/64, NTOK/64), 256>>>(processed, NP, rus, w1, b1,
                                                 hid, NMLP, NCOMB);
    k_mlp2<<<NTOK/16, 256>>>(w2, b2, out);
}